// round 16
// baseline (speedup 1.0000x reference)
#include <cuda_runtime.h>
#include <climits>

#define NB 32
#define H 512
#define W 512
#define C 3
#define OUT 400
#define THRESH 0.7f

#define BPB 16                      // bounds blocks per batch
#define ROWS_PER_BLK (H / BPB)      // 32
#define TB 256
#define VPT 16                      // float4 loads per thread (MLP=16)

// Per-block partial bbox: rmin, rmax, cmin, cmax. Plain-stored every launch.
__device__ int g_part[NB * BPB][4];
// Coordinate tables (separate arrays: row loads warp-uniform, col loads
// 1-line coalesced — measured-good in R1/R15).
__device__ int   g_i0[2][NB][OUT];     // axis 0 = rows, axis 1 = cols
__device__ int   g_i1[2][NB][OUT];
__device__ float g_wt[2][NB][OUT];

__global__ void bounds_kernel(const float* __restrict__ tensor) {
    int blk  = blockIdx.x;
    int b    = blk / BPB;
    int rb   = blk % BPB;
    int row0 = rb * ROWS_PER_BLK;

    const float4* base =
        (const float4*)(tensor + ((size_t)b * H + row0) * W);

    // Front-batched loads: 16 independent LDG.128 per thread (MLP=16).
    float4 v[VPT];
    #pragma unroll
    for (int k = 0; k < VPT; k++)
        v[k] = base[threadIdx.x + k * TB];

    int rmin = INT_MAX, rmax = -1, cmin = INT_MAX, cmax = -1;

    #pragma unroll
    for (int k = 0; k < VPT; k++) {
        int j = threadIdx.x + k * TB;
        int r = j >> 7;            // 128 float4s per row
        int c = (j & 127) << 2;
        bool any = false;
        if (v[k].x > THRESH) { any = true; cmin = min(cmin, c    ); cmax = max(cmax, c    ); }
        if (v[k].y > THRESH) { any = true; cmin = min(cmin, c + 1); cmax = max(cmax, c + 1); }
        if (v[k].z > THRESH) { any = true; cmin = min(cmin, c + 2); cmax = max(cmax, c + 2); }
        if (v[k].w > THRESH) { any = true; cmin = min(cmin, c + 3); cmax = max(cmax, c + 3); }
        if (any) {
            int rr = row0 + r;
            rmin = min(rmin, rr);
            rmax = max(rmax, rr);
        }
    }

    #pragma unroll
    for (int o = 16; o > 0; o >>= 1) {
        rmin = min(rmin, __shfl_xor_sync(0xFFFFFFFFu, rmin, o));
        rmax = max(rmax, __shfl_xor_sync(0xFFFFFFFFu, rmax, o));
        cmin = min(cmin, __shfl_xor_sync(0xFFFFFFFFu, cmin, o));
        cmax = max(cmax, __shfl_xor_sync(0xFFFFFFFFu, cmax, o));
    }

    __shared__ int s[4][TB / 32];
    int wid = threadIdx.x >> 5, lid = threadIdx.x & 31;
    if (lid == 0) { s[0][wid] = rmin; s[1][wid] = rmax; s[2][wid] = cmin; s[3][wid] = cmax; }
    __syncthreads();
    if (threadIdx.x == 0) {
        #pragma unroll
        for (int i = 1; i < TB / 32; i++) {
            rmin = min(rmin, s[0][i]); rmax = max(rmax, s[1][i]);
            cmin = min(cmin, s[2][i]); cmax = max(cmax, s[3][i]);
        }
        g_part[blk][0] = rmin;
        g_part[blk][1] = rmax;
        g_part[blk][2] = cmin;
        g_part[blk][3] = cmax;
    }
}

// Inline replica of _axis_coords (float32 op order preserved).
// Handles the all-False-mask case: jnp.argmax on all-False gives (0, n-1).
__device__ __forceinline__ void axis_coords(int lo, int hi, int i,
                                            int& i0g, int& i1g, float& w) {
    if (hi < lo) { lo = 0; hi = H - 1; }   // H == W == 512
    float size = (float)(hi - lo);
    float src  = ((float)i + 0.5f) * size / (float)OUT - 0.5f;
    float mx   = fmaxf(size - 1.0f, 0.0f);
    src = fminf(fmaxf(src, 0.0f), mx);
    int   i0 = (int)floorf(src);
    int   i1 = min(i0 + 1, max(hi - lo - 1, 0));
    w = src - (float)i0;
    i0g = lo + i0;
    i1g = lo + i1;
}

// One block per batch: reduce bbox partials, then fill both coord tables.
__global__ __launch_bounds__(256) void coords_kernel() {
    int b = blockIdx.x;
    __shared__ int sb[4];

    if (threadIdx.x < 32) {
        int rmin = INT_MAX, rmax = -1, cmin = INT_MAX, cmax = -1;
        if (threadIdx.x < BPB) {
            const int* p = g_part[b * BPB + threadIdx.x];
            rmin = p[0]; rmax = p[1]; cmin = p[2]; cmax = p[3];
        }
        #pragma unroll
        for (int o = 8; o > 0; o >>= 1) {
            rmin = min(rmin, __shfl_xor_sync(0xFFFFFFFFu, rmin, o));
            rmax = max(rmax, __shfl_xor_sync(0xFFFFFFFFu, rmax, o));
            cmin = min(cmin, __shfl_xor_sync(0xFFFFFFFFu, cmin, o));
            cmax = max(cmax, __shfl_xor_sync(0xFFFFFFFFu, cmax, o));
        }
        if (threadIdx.x == 0) {
            sb[0] = rmin; sb[1] = rmax; sb[2] = cmin; sb[3] = cmax;
        }
    }
    __syncthreads();

    int rlo = sb[0], rhi = sb[1], clo = sb[2], chi = sb[3];

    for (int t = threadIdx.x; t < 2 * OUT; t += 256) {
        int axis = t / OUT;
        int i    = t - axis * OUT;
        int i0, i1; float w;
        if (axis == 0) {
            axis_coords(rlo, rhi, i, i0, i1, w);
        } else {
            axis_coords(clo, chi, i, i0, i1, w);
        }
        g_i0[axis][b][i] = i0;
        g_i1[axis][b][i] = i1;
        g_wt[axis][b][i] = w;
    }
}

// R1's measured-best resize body, wave-collapsed: 1184 blocks (one wave,
// 8 blocks/SM), each owning a contiguous pixel chunk.
#define RZB 1184
#define TOTALPX (NB * OUT * OUT)                 // 5,120,000
#define CHUNK ((TOTALPX + RZB - 1) / RZB)        // 4325

__global__ void resize_kernel(const float* __restrict__ img,
                              float* __restrict__ out) {
    int start = blockIdx.x * CHUNK;
    int end   = start + CHUNK;
    if (end > TOTALPX) end = TOTALPX;

    for (int idx = start + threadIdx.x; idx < end; idx += 256) {
        int c = idx % OUT;
        int t = idx / OUT;
        int r = t % OUT;
        int b = t / OUT;

        int   r0 = g_i0[0][b][r];
        int   r1 = g_i1[0][b][r];
        float wr = g_wt[0][b][r];
        int   c0 = g_i0[1][b][c];
        int   c1 = g_i1[1][b][c];
        float wc = g_wt[1][b][c];

        const float* base = img + (size_t)b * H * W * C;
        const float* p00 = base + ((size_t)r0 * W + c0) * C;
        const float* p01 = base + ((size_t)r0 * W + c1) * C;
        const float* p10 = base + ((size_t)r1 * W + c0) * C;
        const float* p11 = base + ((size_t)r1 * W + c1) * C;

        float omwc = 1.0f - wc;
        float omwr = 1.0f - wr;

        float* o = out + (size_t)idx * C;
        #pragma unroll
        for (int ch = 0; ch < C; ch++) {
            float a00 = __ldg(p00 + ch);
            float a01 = __ldg(p01 + ch);
            float a10 = __ldg(p10 + ch);
            float a11 = __ldg(p11 + ch);
            float topv = a00 * omwc + a01 * wc;
            float botv = a10 * omwc + a11 * wc;
            o[ch] = topv * omwr + botv * wr;
        }
    }
}

extern "C" void kernel_launch(void* const* d_in, const int* in_sizes, int n_in,
                              void* d_out, int out_size) {
    // Input-order detection: image has 25,165,824 elems, tensor 8,388,608.
    const float* image  = (const float*)d_in[0];
    const float* tensor = (const float*)d_in[1];
    if (n_in >= 2 && in_sizes[0] < in_sizes[1]) {
        image  = (const float*)d_in[1];
        tensor = (const float*)d_in[0];
    }
    float* out = (float*)d_out;

    bounds_kernel<<<NB * BPB, TB>>>(tensor);
    coords_kernel<<<NB, 256>>>();
    resize_kernel<<<RZB, 256>>>(image, out);
}